// round 16
// baseline (speedup 1.0000x reference)
#include <cuda_runtime.h>
#include <cuda_fp16.h>
#include <float.h>
#include <math.h>
#include <stdint.h>

// ---------------- problem constants ----------------
#define N_TRAIN 65536
#define N_TEST  4096
#define DIM     512
#define KNN     5
#define CAND    5                    // per-thread candidate depth (4 thr/row)
#define SEL     20                   // rescored candidates per row
#define NCTAS   296                  // = 2 x 148 SMs, equal-area jobs
#define NSLOT   12                   // max CTAs covering one m-tile
#define SLOTW   20                   // candidates per (row, slot) = 4 x CAND
#define CPR     (NSLOT * SLOTW)      // 240 candidate slots per row

// ---------------- device scratch ----------------
__device__ __half g_xtr_h[(size_t)N_TRAIN * DIM];   // 64 MB
__device__ __half g_xte_h[(size_t)N_TEST * DIM];    // 4 MB
__device__ float g_x2[N_TRAIN];
__device__ float g_cd[(size_t)N_TEST * CPR];
__device__ int   g_ci[(size_t)N_TEST * CPR];

// ---------------- smem layout (bytes) ----------------
#define A_STRIDE 1040                       // (512+8) half per row
#define B_STRIDE 144                        // 128 B data + 16 B pad
#define B_STAGE  (128 * B_STRIDE)           // 18432
#define SM_A   0                            // 128*1040 = 133120
#define SM_B   133120                       // 3 stages = 55296
#define SM_SC  188416                       // half2 scores 128 rows x 66 h2 = 33792
#define SM_X2  222208                       // 64 half2 = 256
#define SMEM_TOTAL 222464

__device__ __forceinline__ uint32_t smem_u32(const void* p) {
    uint32_t a;
    asm("{ .reg .u64 t; cvta.to.shared.u64 t, %1; cvt.u32.u64 %0, t; }"
        : "=r"(a) : "l"(p));
    return a;
}
#define CP_ASYNC16(dst, src) \
    asm volatile("cp.async.cg.shared.global [%0], [%1], 16;" :: "r"(dst), "l"(src))
#define CP_COMMIT() asm volatile("cp.async.commit_group;" ::: "memory")
#define CP_WAIT1()  asm volatile("cp.async.wait_group 1;" ::: "memory")

#define LDMATRIX_X4(r0, r1, r2, r3, addr)                                  \
    asm volatile("ldmatrix.sync.aligned.m8n8.x4.shared.b16 "               \
                 "{%0,%1,%2,%3}, [%4];"                                    \
                 : "=r"(r0), "=r"(r1), "=r"(r2), "=r"(r3) : "r"(addr))

// fp16 inputs, fp16 accumulators
#define MMA16816H(c, a, b0_, b1_)                                          \
    asm volatile("mma.sync.aligned.m16n8k16.row.col.f16.f16.f16.f16 "      \
                 "{%0,%1}, {%2,%3,%4,%5}, {%6,%7}, {%0,%1};"               \
                 : "+r"((c)[0]), "+r"((c)[1])                              \
                 : "r"((a)[0]), "r"((a)[1]), "r"((a)[2]), "r"((a)[3]),     \
                   "r"(b0_), "r"(b1_))

#define INSERT5(dA, iA, sv, nv)                                  \
  do {                                                           \
    float _s = (sv); int _n = (nv);                              \
    _Pragma("unroll")                                            \
    for (int _p = CAND - 1; _p >= 0; _p--) {                     \
      if (_p > 0 && _s < dA[_p - 1]) {                           \
        dA[_p] = dA[_p - 1]; iA[_p] = iA[_p - 1];                \
      } else { dA[_p] = _s; iA[_p] = _n; break; }                \
    }                                                            \
  } while (0)

// Job partition arithmetic: tile space 16384 = 32 m-tiles x 512 n-tiles,
// CTA j owns tiles [s_j, e_j) with s_j = floor(2048*j/37).
__device__ __forceinline__ int job_start(int j) { return (j * 2048) / 37; }
__device__ __forceinline__ int first_cta(int M) {
    return (512 * M * 37 + 36) >> 11;
}
__device__ __forceinline__ int last_cta(int M) {
    return (512 * (M + 1) * 37 - 1) >> 11;
}

// Exact skip threshold: v >= ru(worst)  ==>  float(v) >= worst.
__device__ __forceinline__ __half2 make_thr2(float worst) {
    return __half2half2(__float2half_ru(fminf(worst, 60000.0f)));
}

// ---------------------------------------------------------------------------
// Kernel 1: fused fp16 conversion for train+test (+ exact fp32 train norms).
// ---------------------------------------------------------------------------
__global__ void conv_kernel(const float* __restrict__ Xtr,
                            const float* __restrict__ Xte) {
    int row  = blockIdx.x * 8 + (threadIdx.x >> 5);
    int lane = threadIdx.x & 31;
    const bool is_test = row >= N_TRAIN;
    const int  r       = is_test ? row - N_TRAIN : row;
    const float4* p = reinterpret_cast<const float4*>(
        (is_test ? Xte : Xtr) + (size_t)r * DIM);
    uint2* o = reinterpret_cast<uint2*>(
        (is_test ? g_xte_h : g_xtr_h) + (size_t)r * DIM);
    float s = 0.f;
#pragma unroll
    for (int i = 0; i < 4; i++) {
        float4 v = p[lane + 32 * i];
        s += v.x * v.x + v.y * v.y + v.z * v.z + v.w * v.w;
        __half2 h0 = __float22half2_rn(make_float2(v.x, v.y));
        __half2 h1 = __float22half2_rn(make_float2(v.z, v.w));
        uint2 w;
        w.x = *reinterpret_cast<uint32_t*>(&h0);
        w.y = *reinterpret_cast<uint32_t*>(&h1);
        o[lane + 32 * i] = w;
    }
    if (!is_test) {
#pragma unroll
        for (int off = 16; off; off >>= 1)
            s += __shfl_xor_sync(0xFFFFFFFFu, s, off);
        if (lane == 0) g_x2[r] = s;
    }
}

// ---------------------------------------------------------------------------
// Kernel 2: fp16 mma.sync GEMM, 1024 threads = 32 warps (8 warps/SMSP).
// Warp (wm=wid&7, wn=wid>>3) owns a 16x32 sub-tile of the 128x128 tile.
// Same 296-job schedule, 3-stage cp.async ring, single-barrier half2
// epilogue (threads < 512 scan: 4 threads/row, depth 5).
// ---------------------------------------------------------------------------
__global__ void __launch_bounds__(1024, 1)
knn_gemm_kernel() {
    extern __shared__ __align__(16) char smem[];
    const uint32_t sb = smem_u32(smem);

    const int tid  = threadIdx.x;
    const int wid  = tid >> 5;
    const int lane = tid & 31;
    const int wm   = wid & 7;     // 0..7  : 16-row group
    const int wn   = wid >> 3;    // 0..3  : 32-col group
    const int j    = blockIdx.x;

    const int ts = job_start(j);
    const int te = job_start(j + 1);

    __half2* hsc = reinterpret_cast<__half2*>(smem + SM_SC);   // stride 66/row
    __half2* x2h = reinterpret_cast<__half2*>(smem + SM_X2);   // 64 half2

    // ldmatrix lane addresses (segment-invariant)
    const uint32_t a_lane = sb + SM_A +
        (uint32_t)(wm * 16 + (lane & 7) + ((lane >> 3) & 1) * 8) * A_STRIDE +
        (uint32_t)(lane >> 4) * 16;
    const uint32_t b_row  = (lane & 7) + (lane >> 4) * 8;
    const uint32_t b_koff = ((lane >> 3) & 1) * 16;

    const __half2 m2 = __float2half2_rn(-2.0f);

    const int mA = ts >> 9, mB = (te - 1) >> 9;
    for (int segm = mA; segm <= mB; segm++) {
        const int t0  = (segm << 9) > ts ? (segm << 9) : ts;
        const int t1  = ((segm + 1) << 9) < te ? ((segm + 1) << 9) : te;
        const int nt0 = t0 & 511;          // first n-tile in this segment
        const int ntn = t1 - t0;           // n-tile count
        const int m0  = segm * 128;

        // ---- A resident (128 x 512 half) for this m-tile ----
#pragma unroll
        for (int i = tid; i < 8192; i += 1024) {
            int row = i >> 6, c16 = i & 63;
            const char* src = (const char*)(g_xte_h +
                (size_t)(m0 + row) * DIM + c16 * 8);
            CP_ASYNC16(sb + SM_A + row * A_STRIDE + c16 * 16, src);
        }
        CP_COMMIT();

        // ---- fresh register candidate lists (threads < 512 use them) ----
        float cd[CAND]; int cix[CAND];
#pragma unroll
        for (int q = 0; q < CAND; q++) { cd[q] = FLT_MAX; cix[q] = 0x7FFFFFFF; }
        float worst = FLT_MAX;
        __half2 thr2 = make_thr2(worst);

        // ---- B chunk loader: g = (nt = g>>3, kt = g&7), 128 rows x 128 B ----
        auto load_chunk = [&](int g) {
            if (g < ntn * 8) {
                const int ntc = nt0 + (g >> 3), ktc = g & 7;
                const uint32_t dbase = sb + SM_B + (uint32_t)(g % 3) * B_STAGE;
                int row = tid >> 3, c16 = tid & 7;   // 1024 x 16B = 16 KB
                const char* src = (const char*)(g_xtr_h +
                    (size_t)(ntc * 128 + row) * DIM + ktc * 64 + c16 * 8);
                CP_ASYNC16(dbase + row * B_STRIDE + c16 * 16, src);
            }
            CP_COMMIT();
        };
        load_chunk(0);
        load_chunk(1);

        for (int nt = 0; nt < ntn; nt++) {
            const int n0 = (nt0 + nt) * 128;
            if (tid < 64)
                x2h[tid] = __floats2half2_rn(g_x2[n0 + 2 * tid],
                                             g_x2[n0 + 2 * tid + 1]);

            uint32_t acc[4][2];
#pragma unroll
            for (int ni = 0; ni < 4; ni++) { acc[ni][0] = 0u; acc[ni][1] = 0u; }

            for (int kt = 0; kt < 8; kt++) {
                const int g = nt * 8 + kt;
                CP_WAIT1();
                __syncthreads();
                load_chunk(g + 2);

                const uint32_t bbuf = sb + SM_B + (uint32_t)(g % 3) * B_STAGE;
#pragma unroll
                for (int ks = 0; ks < 4; ks++) {
                    const uint32_t kb = (uint32_t)kt * 128 + (uint32_t)ks * 32;
                    uint32_t a[4];
                    LDMATRIX_X4(a[0], a[1], a[2], a[3], a_lane + kb);
                    uint32_t b[2][4];
#pragma unroll
                    for (int np = 0; np < 2; np++)
                        LDMATRIX_X4(b[np][0], b[np][1], b[np][2], b[np][3],
                                    bbuf + (uint32_t)(wn * 32 + np * 16 + b_row) * B_STRIDE +
                                    (uint32_t)ks * 32 + b_koff);
#pragma unroll
                    for (int np = 0; np < 2; np++) {
                        MMA16816H(acc[np * 2 + 0], a, b[np][0], b[np][1]);
                        MMA16816H(acc[np * 2 + 1], a, b[np][2], b[np][3]);
                    }
                }
            }

            // ---- epilogue: HFMA2 score write, one barrier, LDS.64 scan ----
            {
                const int r   = wm * 16 + (lane >> 2);
                const int ch0 = wn * 16 + (lane & 3);     // half2 column index
#pragma unroll
                for (int ni = 0; ni < 4; ni++) {
                    const int ch = ch0 + ni * 4;
                    const __half2 xp = x2h[ch];
                    hsc[r * 66 + ch] = __hfma2(
                        *reinterpret_cast<__half2*>(&acc[ni][0]), m2, xp);
                    hsc[(r + 8) * 66 + ch] = __hfma2(
                        *reinterpret_cast<__half2*>(&acc[ni][1]), m2, xp);
                }
                __syncthreads();
                if (tid < 512) {
                    const int srow = tid & 127;
                    const int part = tid >> 7;          // 0..3, 32 cols each
                    const uint2* hu = reinterpret_cast<const uint2*>(smem + SM_SC) +
                                      srow * 33 + part * 8;
#pragma unroll 4
                    for (int u = 0; u < 8; u++) {
                        uint2 w = hu[u];
                        __half2 v0 = *reinterpret_cast<__half2*>(&w.x);
                        __half2 v1 = *reinterpret_cast<__half2*>(&w.y);
                        if (!__hbge2(__hmin2(v0, v1), thr2)) {
                            const int n = n0 + part * 32 + 4 * u;
                            const float f0 = __low2float(v0), f1 = __high2float(v0);
                            const float f2 = __low2float(v1), f3 = __high2float(v1);
                            if (f0 < worst) { INSERT5(cd, cix, f0, n);     worst = cd[CAND - 1]; }
                            if (f1 < worst) { INSERT5(cd, cix, f1, n + 1); worst = cd[CAND - 1]; }
                            if (f2 < worst) { INSERT5(cd, cix, f2, n + 2); worst = cd[CAND - 1]; }
                            if (f3 < worst) { INSERT5(cd, cix, f3, n + 3); worst = cd[CAND - 1]; }
                            thr2 = make_thr2(worst);
                        }
                    }
                }
                // no trailing barrier: next hsc/x2h writes are ordered behind
                // the next tile's k-loop __syncthreads chain.
            }
        }

        // ---- flush this segment's candidates into deterministic slot ----
        if (tid < 512) {
            const int slot = j - first_cta(segm);
            const int row = tid & 127, part = tid >> 7;
            const size_t ob = (size_t)(m0 + row) * CPR +
                              (size_t)slot * SLOTW + part * CAND;
#pragma unroll
            for (int q = 0; q < CAND; q++) { g_cd[ob + q] = cd[q]; g_ci[ob + q] = cix[q]; }
        }
        __syncthreads();   // protect hsc/x2h across segment boundary
    }
}

// ---------------------------------------------------------------------------
// Kernel 3: rescue + finalize. One warp per test row, <=240 candidates.
// ---------------------------------------------------------------------------
__global__ void rescue_kernel(const float* __restrict__ Xtr,
                              const float* __restrict__ Xte,
                              const unsigned* __restrict__ yw,
                              float* __restrict__ out) {
    const int m    = blockIdx.x * 8 + (threadIdx.x >> 5);
    const int lane = threadIdx.x & 31;
    if (m >= N_TEST) return;

    // label dtype detection (uniform across threads)
    bool i32ok = true, i64ok = true, f32ok = true;
#pragma unroll
    for (int i = 0; i < 32; i++) {
        unsigned w = yw[i];
        if (w > 9u) i32ok = false;
        if (i & 1) { if (w != 0u) i64ok = false; }
        else       { if (w > 9u)  i64ok = false; }
        float f = __uint_as_float(w);
        if (!(f >= 0.f && f <= 9.f && f == floorf(f))) f32ok = false;
    }
    const int ymode = i64ok ? 1 : (i32ok ? 0 : (f32ok ? 2 : 0));

    // candidate count for this row's m-tile
    const int M   = m >> 7;
    const int cnt = (last_cta(M) - first_cta(M) + 1) * SLOTW;   // <= 240

    // load candidates: 8 per lane, masked
    float cs[8]; int ci_[8];
    const size_t cb = (size_t)m * CPR;
#pragma unroll
    for (int e = 0; e < 8; e++) {
        const int idx = lane + 32 * e;
        const bool ok = idx < cnt;
        cs[e]  = ok ? g_cd[cb + idx] : FLT_MAX;
        ci_[e] = ok ? g_ci[cb + idx] : 0x7FFFFFFF;
    }

    // select top-SEL by approx score (repeated warp argmin)
    int sel[SEL];
#pragma unroll
    for (int it = 0; it < SEL; it++) {
        float bs = cs[0]; int be = 0;
#pragma unroll
        for (int e = 1; e < 8; e++)
            if (cs[e] < bs) { bs = cs[e]; be = e; }
        int pl = lane * 8 + be;
#pragma unroll
        for (int off = 16; off; off >>= 1) {
            float os = __shfl_xor_sync(0xFFFFFFFFu, bs, off);
            int   op = __shfl_xor_sync(0xFFFFFFFFu, pl, off);
            if (os < bs || (os == bs && op < pl)) { bs = os; pl = op; }
        }
        const int wl = pl >> 3, we = pl & 7;
        int v = ci_[0];
#pragma unroll
        for (int e = 1; e < 8; e++) if (we == e) v = ci_[e];
        sel[it] = __shfl_sync(0xFFFFFFFFu, v, wl);
        if (lane == wl) {
#pragma unroll
            for (int e = 0; e < 8; e++) if (we == e) cs[e] = FLT_MAX;
        }
    }

    // exact fp32 rescore of the SEL candidates
    float a[16];
    {
        const float4* tp = reinterpret_cast<const float4*>(
            Xte + (size_t)m * DIM + lane * 16);
#pragma unroll
        for (int u = 0; u < 4; u++) {
            float4 v = tp[u];
            a[u * 4 + 0] = v.x; a[u * 4 + 1] = v.y;
            a[u * 4 + 2] = v.z; a[u * 4 + 3] = v.w;
        }
    }
    float my_s = FLT_MAX; int my_i = 0x7FFFFFFF;
#pragma unroll
    for (int t = 0; t < SEL; t++) {
        const int idx = sel[t];
        const float4* rp = reinterpret_cast<const float4*>(
            Xtr + (size_t)idx * DIM + lane * 16);
        float dot = 0.f;
#pragma unroll
        for (int u = 0; u < 4; u++) {
            float4 v = rp[u];
            dot = fmaf(a[u * 4 + 0], v.x, dot);
            dot = fmaf(a[u * 4 + 1], v.y, dot);
            dot = fmaf(a[u * 4 + 2], v.z, dot);
            dot = fmaf(a[u * 4 + 3], v.w, dot);
        }
#pragma unroll
        for (int off = 16; off; off >>= 1)
            dot += __shfl_xor_sync(0xFFFFFFFFu, dot, off);
        const float s = fmaf(-2.f, dot, __ldg(&g_x2[idx]));
        if (lane == t) { my_s = s; my_i = idx; }
    }

    // top-5 by (score, index), gather labels, mode
    int lab[5];
#pragma unroll
    for (int r = 0; r < 5; r++) {
        float bs = my_s; int bi = my_i;
#pragma unroll
        for (int off = 16; off; off >>= 1) {
            float os = __shfl_xor_sync(0xFFFFFFFFu, bs, off);
            int   oi = __shfl_xor_sync(0xFFFFFFFFu, bi, off);
            if (os < bs || (os == bs && oi < bi)) { bs = os; bi = oi; }
        }
        if (my_s == bs && my_i == bi) my_s = FLT_MAX;
        unsigned w = (ymode == 1) ? yw[2 * (size_t)bi] : yw[bi];
        lab[r] = (ymode == 2) ? (int)__uint_as_float(w) : (int)w;
    }

    if (lane == 0) {
        int best = 0x7FFFFFFF, bc = 0;
#pragma unroll
        for (int q = 0; q < 5; q++) {
            int c = 0;
#pragma unroll
            for (int r = 0; r < 5; r++) c += (lab[r] == lab[q]);
            if (c > bc || (c == bc && lab[q] < best)) { bc = c; best = lab[q]; }
        }
        out[m] = (float)best;
    }
}

// ---------------------------------------------------------------------------
extern "C" void kernel_launch(void* const* d_in, const int* in_sizes, int n_in,
                              void* d_out, int out_size) {
    const float*    Xtr = (const float*)d_in[0];
    const float*    Xte = (const float*)d_in[1];
    const unsigned* yw  = (const unsigned*)d_in[2];
    float*          out = (float*)d_out;

    cudaFuncSetAttribute(knn_gemm_kernel,
                         cudaFuncAttributeMaxDynamicSharedMemorySize, SMEM_TOTAL);

    conv_kernel<<<(N_TRAIN + N_TEST) / 8, 256>>>(Xtr, Xte);
    knn_gemm_kernel<<<NCTAS, 1024, SMEM_TOTAL>>>();
    rescue_kernel<<<N_TEST / 8, 256>>>(Xtr, Xte, yw, out);
}

// round 17
// speedup vs baseline: 1.0886x; 1.0886x over previous
#include <cuda_runtime.h>
#include <cuda_fp16.h>
#include <float.h>
#include <math.h>
#include <stdint.h>

// ---------------- problem constants ----------------
#define N_TRAIN 65536
#define N_TEST  4096
#define DIM     512
#define KNN     5
#define CAND    5                    // per-thread candidate depth (4 thr/row)
#define SEL     20                   // rescored candidates per row
#define NCTAS   148                  // = 1 x 148 SMs, equal-area jobs, 1 wave
#define NSLOT   6                    // max CTAs covering one m-tile
#define SLOTW   20                   // candidates per (row, slot) = 4 x CAND
#define CPR     (NSLOT * SLOTW)      // 120 candidate slots per row

// ---------------- device scratch ----------------
__device__ __half g_xtr_h[(size_t)N_TRAIN * DIM];   // 64 MB
__device__ __half g_xte_h[(size_t)N_TEST * DIM];    // 4 MB
__device__ float g_x2[N_TRAIN];
__device__ float g_cd[(size_t)N_TEST * CPR];
__device__ int   g_ci[(size_t)N_TEST * CPR];

// ---------------- smem layout (bytes) ----------------
#define A_STRIDE 1040                       // (512+8) half per row
#define B_STRIDE 144                        // 128 B data + 16 B pad
#define B_STAGE  (128 * B_STRIDE)           // 18432
#define SM_A   0                            // 128*1040 = 133120
#define SM_B   133120                       // 3 stages = 55296
#define SM_SC  188416                       // half2 scores 128 rows x 66 h2 = 33792
#define SM_X2  222208                       // 64 half2 = 256
#define SMEM_TOTAL 222464

__device__ __forceinline__ uint32_t smem_u32(const void* p) {
    uint32_t a;
    asm("{ .reg .u64 t; cvta.to.shared.u64 t, %1; cvt.u32.u64 %0, t; }"
        : "=r"(a) : "l"(p));
    return a;
}
#define CP_ASYNC16(dst, src) \
    asm volatile("cp.async.cg.shared.global [%0], [%1], 16;" :: "r"(dst), "l"(src))
#define CP_COMMIT() asm volatile("cp.async.commit_group;" ::: "memory")
#define CP_WAIT1()  asm volatile("cp.async.wait_group 1;" ::: "memory")

#define LDMATRIX_X4(r0, r1, r2, r3, addr)                                  \
    asm volatile("ldmatrix.sync.aligned.m8n8.x4.shared.b16 "               \
                 "{%0,%1,%2,%3}, [%4];"                                    \
                 : "=r"(r0), "=r"(r1), "=r"(r2), "=r"(r3) : "r"(addr))

// fp16 inputs, fp16 accumulators
#define MMA16816H(c, a, b0_, b1_)                                          \
    asm volatile("mma.sync.aligned.m16n8k16.row.col.f16.f16.f16.f16 "      \
                 "{%0,%1}, {%2,%3,%4,%5}, {%6,%7}, {%0,%1};"               \
                 : "+r"((c)[0]), "+r"((c)[1])                              \
                 : "r"((a)[0]), "r"((a)[1]), "r"((a)[2]), "r"((a)[3]),     \
                   "r"(b0_), "r"(b1_))

#define INSERT5(dA, iA, sv, nv)                                  \
  do {                                                           \
    float _s = (sv); int _n = (nv);                              \
    _Pragma("unroll")                                            \
    for (int _p = CAND - 1; _p >= 0; _p--) {                     \
      if (_p > 0 && _s < dA[_p - 1]) {                           \
        dA[_p] = dA[_p - 1]; iA[_p] = iA[_p - 1];                \
      } else { dA[_p] = _s; iA[_p] = _n; break; }                \
    }                                                            \
  } while (0)

// Job partition arithmetic: tile space 16384 = 32 m-tiles x 512 n-tiles,
// CTA j owns tiles [s_j, e_j) with s_j = floor(4096*j/37)  (148 CTAs).
__device__ __forceinline__ int job_start(int j) { return (j * 4096) / 37; }
// CTA containing tile t is floor((37*t + 36)/4096).
__device__ __forceinline__ int first_cta(int M) {
    return (18944 * M + 36) >> 12;          // 18944 = 512*37
}
__device__ __forceinline__ int last_cta(int M) {
    return (18944 * (M + 1) - 1) >> 12;
}

// Exact skip threshold: v >= ru(worst)  ==>  float(v) >= worst.
__device__ __forceinline__ __half2 make_thr2(float worst) {
    return __half2half2(__float2half_ru(fminf(worst, 60000.0f)));
}

// ---------------------------------------------------------------------------
// Kernel 1: fused fp16 conversion for train+test (+ exact fp32 train norms).
// ---------------------------------------------------------------------------
__global__ void conv_kernel(const float* __restrict__ Xtr,
                            const float* __restrict__ Xte) {
    int row  = blockIdx.x * 8 + (threadIdx.x >> 5);
    int lane = threadIdx.x & 31;
    const bool is_test = row >= N_TRAIN;
    const int  r       = is_test ? row - N_TRAIN : row;
    const float4* p = reinterpret_cast<const float4*>(
        (is_test ? Xte : Xtr) + (size_t)r * DIM);
    uint2* o = reinterpret_cast<uint2*>(
        (is_test ? g_xte_h : g_xtr_h) + (size_t)r * DIM);
    float s = 0.f;
#pragma unroll
    for (int i = 0; i < 4; i++) {
        float4 v = p[lane + 32 * i];
        s += v.x * v.x + v.y * v.y + v.z * v.z + v.w * v.w;
        __half2 h0 = __float22half2_rn(make_float2(v.x, v.y));
        __half2 h1 = __float22half2_rn(make_float2(v.z, v.w));
        uint2 w;
        w.x = *reinterpret_cast<uint32_t*>(&h0);
        w.y = *reinterpret_cast<uint32_t*>(&h1);
        o[lane + 32 * i] = w;
    }
    if (!is_test) {
#pragma unroll
        for (int off = 16; off; off >>= 1)
            s += __shfl_xor_sync(0xFFFFFFFFu, s, off);
        if (lane == 0) g_x2[r] = s;
    }
}

// ---------------------------------------------------------------------------
// Kernel 2: fp16 mma.sync GEMM, 512 threads = 16 warps (4 warps/SMSP —
// measured HMMA pipe saturation point). Warp (wm=wid&7, wn=wid>>3) owns a
// 16x64 sub-tile of the 128x128 score tile. 148 equal-area jobs (1 wave),
// 3-stage cp.async ring, single-barrier half2 epilogue (4 thr/row, depth 5).
// ---------------------------------------------------------------------------
__global__ void __launch_bounds__(512, 1)
knn_gemm_kernel() {
    extern __shared__ __align__(16) char smem[];
    const uint32_t sb = smem_u32(smem);

    const int tid  = threadIdx.x;
    const int wid  = tid >> 5;
    const int lane = tid & 31;
    const int wm   = wid & 7;
    const int wn   = wid >> 3;
    const int j    = blockIdx.x;

    const int ts = job_start(j);
    const int te = job_start(j + 1);

    __half2* hsc = reinterpret_cast<__half2*>(smem + SM_SC);   // stride 66/row
    __half2* x2h = reinterpret_cast<__half2*>(smem + SM_X2);   // 64 half2

    // ldmatrix lane addresses (segment-invariant)
    const uint32_t a_lane = sb + SM_A +
        (uint32_t)(wm * 16 + (lane & 7) + ((lane >> 3) & 1) * 8) * A_STRIDE +
        (uint32_t)(lane >> 4) * 16;
    const uint32_t b_row  = (lane & 7) + (lane >> 4) * 8;
    const uint32_t b_koff = ((lane >> 3) & 1) * 16;

    const __half2 m2 = __float2half2_rn(-2.0f);

    const int mA = ts >> 9, mB = (te - 1) >> 9;
    for (int segm = mA; segm <= mB; segm++) {
        const int t0  = (segm << 9) > ts ? (segm << 9) : ts;
        const int t1  = ((segm + 1) << 9) < te ? ((segm + 1) << 9) : te;
        const int nt0 = t0 & 511;          // first n-tile in this segment
        const int ntn = t1 - t0;           // n-tile count
        const int m0  = segm * 128;

        // ---- A resident (128 x 512 half) for this m-tile ----
#pragma unroll
        for (int i = tid; i < 8192; i += 512) {
            int row = i >> 6, c16 = i & 63;
            const char* src = (const char*)(g_xte_h +
                (size_t)(m0 + row) * DIM + c16 * 8);
            CP_ASYNC16(sb + SM_A + row * A_STRIDE + c16 * 16, src);
        }
        CP_COMMIT();

        // ---- fresh register candidate lists ----
        float cd[CAND]; int cix[CAND];
#pragma unroll
        for (int q = 0; q < CAND; q++) { cd[q] = FLT_MAX; cix[q] = 0x7FFFFFFF; }
        float worst = FLT_MAX;
        __half2 thr2 = make_thr2(worst);

        // ---- B chunk loader: g = (nt = g>>3, kt = g&7), 128 rows x 128 B ----
        auto load_chunk = [&](int g) {
            if (g < ntn * 8) {
                const int ntc = nt0 + (g >> 3), ktc = g & 7;
                const uint32_t dbase = sb + SM_B + (uint32_t)(g % 3) * B_STAGE;
#pragma unroll
                for (int e = 0; e < 2; e++) {
                    int id  = tid * 2 + e;
                    int row = id >> 3, c16 = id & 7;
                    const char* src = (const char*)(g_xtr_h +
                        (size_t)(ntc * 128 + row) * DIM + ktc * 64 + c16 * 8);
                    CP_ASYNC16(dbase + row * B_STRIDE + c16 * 16, src);
                }
            }
            CP_COMMIT();
        };
        load_chunk(0);
        load_chunk(1);

        for (int nt = 0; nt < ntn; nt++) {
            const int n0 = (nt0 + nt) * 128;
            if (tid < 64)
                x2h[tid] = __floats2half2_rn(g_x2[n0 + 2 * tid],
                                             g_x2[n0 + 2 * tid + 1]);

            uint32_t acc[8][2];
#pragma unroll
            for (int ni = 0; ni < 8; ni++) { acc[ni][0] = 0u; acc[ni][1] = 0u; }

            for (int kt = 0; kt < 8; kt++) {
                const int g = nt * 8 + kt;
                CP_WAIT1();
                __syncthreads();
                load_chunk(g + 2);

                const uint32_t bbuf = sb + SM_B + (uint32_t)(g % 3) * B_STAGE;
#pragma unroll
                for (int ks = 0; ks < 4; ks++) {
                    const uint32_t kb = (uint32_t)kt * 128 + (uint32_t)ks * 32;
                    uint32_t a[4];
                    LDMATRIX_X4(a[0], a[1], a[2], a[3], a_lane + kb);
                    uint32_t b[4][4];
#pragma unroll
                    for (int np = 0; np < 4; np++)
                        LDMATRIX_X4(b[np][0], b[np][1], b[np][2], b[np][3],
                                    bbuf + (uint32_t)(wn * 64 + np * 16 + b_row) * B_STRIDE +
                                    (uint32_t)ks * 32 + b_koff);
#pragma unroll
                    for (int np = 0; np < 4; np++) {
                        MMA16816H(acc[np * 2 + 0], a, b[np][0], b[np][1]);
                        MMA16816H(acc[np * 2 + 1], a, b[np][2], b[np][3]);
                    }
                }
            }

            // ---- epilogue: HFMA2 score write, one barrier, LDS.64 scan ----
            {
                const int r   = wm * 16 + (lane >> 2);
                const int ch0 = wn * 32 + (lane & 3);     // half2 column index
#pragma unroll
                for (int ni = 0; ni < 8; ni++) {
                    const int ch = ch0 + ni * 4;
                    const __half2 xp = x2h[ch];
                    hsc[r * 66 + ch] = __hfma2(
                        *reinterpret_cast<__half2*>(&acc[ni][0]), m2, xp);
                    hsc[(r + 8) * 66 + ch] = __hfma2(
                        *reinterpret_cast<__half2*>(&acc[ni][1]), m2, xp);
                }
                __syncthreads();
                const int srow = tid & 127;
                const int part = tid >> 7;          // 0..3, 32 cols each
                const uint2* hu = reinterpret_cast<const uint2*>(smem + SM_SC) +
                                  srow * 33 + part * 8;
#pragma unroll 4
                for (int u = 0; u < 8; u++) {
                    uint2 w = hu[u];
                    __half2 v0 = *reinterpret_cast<__half2*>(&w.x);
                    __half2 v1 = *reinterpret_cast<__half2*>(&w.y);
                    if (!__hbge2(__hmin2(v0, v1), thr2)) {
                        const int n = n0 + part * 32 + 4 * u;
                        const float f0 = __low2float(v0), f1 = __high2float(v0);
                        const float f2 = __low2float(v1), f3 = __high2float(v1);
                        if (f0 < worst) { INSERT5(cd, cix, f0, n);     worst = cd[CAND - 1]; }
                        if (f1 < worst) { INSERT5(cd, cix, f1, n + 1); worst = cd[CAND - 1]; }
                        if (f2 < worst) { INSERT5(cd, cix, f2, n + 2); worst = cd[CAND - 1]; }
                        if (f3 < worst) { INSERT5(cd, cix, f3, n + 3); worst = cd[CAND - 1]; }
                        thr2 = make_thr2(worst);
                    }
                }
                // no trailing barrier: next hsc/x2h writes are ordered behind
                // the next tile's k-loop __syncthreads chain.
            }
        }

        // ---- flush this segment's candidates into deterministic slot ----
        {
            const int slot = j - first_cta(segm);
            const int row = tid & 127, part = tid >> 7;
            const size_t ob = (size_t)(m0 + row) * CPR +
                              (size_t)slot * SLOTW + part * CAND;
#pragma unroll
            for (int q = 0; q < CAND; q++) { g_cd[ob + q] = cd[q]; g_ci[ob + q] = cix[q]; }
        }
        __syncthreads();   // protect hsc/x2h across segment boundary
    }
}

// ---------------------------------------------------------------------------
// Kernel 3: rescue + finalize. One warp per test row, <=120 candidates.
// ---------------------------------------------------------------------------
__global__ void rescue_kernel(const float* __restrict__ Xtr,
                              const float* __restrict__ Xte,
                              const unsigned* __restrict__ yw,
                              float* __restrict__ out) {
    const int m    = blockIdx.x * 8 + (threadIdx.x >> 5);
    const int lane = threadIdx.x & 31;
    if (m >= N_TEST) return;

    // label dtype detection (uniform across threads)
    bool i32ok = true, i64ok = true, f32ok = true;
#pragma unroll
    for (int i = 0; i < 32; i++) {
        unsigned w = yw[i];
        if (w > 9u) i32ok = false;
        if (i & 1) { if (w != 0u) i64ok = false; }
        else       { if (w > 9u)  i64ok = false; }
        float f = __uint_as_float(w);
        if (!(f >= 0.f && f <= 9.f && f == floorf(f))) f32ok = false;
    }
    const int ymode = i64ok ? 1 : (i32ok ? 0 : (f32ok ? 2 : 0));

    // candidate count for this row's m-tile
    const int M   = m >> 7;
    const int cnt = (last_cta(M) - first_cta(M) + 1) * SLOTW;   // <= 120

    // load candidates: 4 per lane, masked
    float cs[4]; int ci_[4];
    const size_t cb = (size_t)m * CPR;
#pragma unroll
    for (int e = 0; e < 4; e++) {
        const int idx = lane + 32 * e;
        const bool ok = idx < cnt;
        cs[e]  = ok ? g_cd[cb + idx] : FLT_MAX;
        ci_[e] = ok ? g_ci[cb + idx] : 0x7FFFFFFF;
    }

    // select top-SEL by approx score (repeated warp argmin)
    int sel[SEL];
#pragma unroll
    for (int it = 0; it < SEL; it++) {
        float bs = cs[0]; int be = 0;
#pragma unroll
        for (int e = 1; e < 4; e++)
            if (cs[e] < bs) { bs = cs[e]; be = e; }
        int pl = lane * 4 + be;
#pragma unroll
        for (int off = 16; off; off >>= 1) {
            float os = __shfl_xor_sync(0xFFFFFFFFu, bs, off);
            int   op = __shfl_xor_sync(0xFFFFFFFFu, pl, off);
            if (os < bs || (os == bs && op < pl)) { bs = os; pl = op; }
        }
        const int wl = pl >> 2, we = pl & 3;
        int v = ci_[0];
#pragma unroll
        for (int e = 1; e < 4; e++) if (we == e) v = ci_[e];
        sel[it] = __shfl_sync(0xFFFFFFFFu, v, wl);
        if (lane == wl) {
#pragma unroll
            for (int e = 0; e < 4; e++) if (we == e) cs[e] = FLT_MAX;
        }
    }

    // exact fp32 rescore of the SEL candidates
    float a[16];
    {
        const float4* tp = reinterpret_cast<const float4*>(
            Xte + (size_t)m * DIM + lane * 16);
#pragma unroll
        for (int u = 0; u < 4; u++) {
            float4 v = tp[u];
            a[u * 4 + 0] = v.x; a[u * 4 + 1] = v.y;
            a[u * 4 + 2] = v.z; a[u * 4 + 3] = v.w;
        }
    }
    float my_s = FLT_MAX; int my_i = 0x7FFFFFFF;
#pragma unroll
    for (int t = 0; t < SEL; t++) {
        const int idx = sel[t];
        const float4* rp = reinterpret_cast<const float4*>(
            Xtr + (size_t)idx * DIM + lane * 16);
        float dot = 0.f;
#pragma unroll
        for (int u = 0; u < 4; u++) {
            float4 v = rp[u];
            dot = fmaf(a[u * 4 + 0], v.x, dot);
            dot = fmaf(a[u * 4 + 1], v.y, dot);
            dot = fmaf(a[u * 4 + 2], v.z, dot);
            dot = fmaf(a[u * 4 + 3], v.w, dot);
        }
#pragma unroll
        for (int off = 16; off; off >>= 1)
            dot += __shfl_xor_sync(0xFFFFFFFFu, dot, off);
        const float s = fmaf(-2.f, dot, __ldg(&g_x2[idx]));
        if (lane == t) { my_s = s; my_i = idx; }
    }

    // top-5 by (score, index), gather labels, mode
    int lab[5];
#pragma unroll
    for (int r = 0; r < 5; r++) {
        float bs = my_s; int bi = my_i;
#pragma unroll
        for (int off = 16; off; off >>= 1) {
            float os = __shfl_xor_sync(0xFFFFFFFFu, bs, off);
            int   oi = __shfl_xor_sync(0xFFFFFFFFu, bi, off);
            if (os < bs || (os == bs && oi < bi)) { bs = os; bi = oi; }
        }
        if (my_s == bs && my_i == bi) my_s = FLT_MAX;
        unsigned w = (ymode == 1) ? yw[2 * (size_t)bi] : yw[bi];
        lab[r] = (ymode == 2) ? (int)__uint_as_float(w) : (int)w;
    }

    if (lane == 0) {
        int best = 0x7FFFFFFF, bc = 0;
#pragma unroll
        for (int q = 0; q < 5; q++) {
            int c = 0;
#pragma unroll
            for (int r = 0; r < 5; r++) c += (lab[r] == lab[q]);
            if (c > bc || (c == bc && lab[q] < best)) { bc = c; best = lab[q]; }
        }
        out[m] = (float)best;
    }
}

// ---------------------------------------------------------------------------
extern "C" void kernel_launch(void* const* d_in, const int* in_sizes, int n_in,
                              void* d_out, int out_size) {
    const float*    Xtr = (const float*)d_in[0];
    const float*    Xte = (const float*)d_in[1];
    const unsigned* yw  = (const unsigned*)d_in[2];
    float*          out = (float*)d_out;

    cudaFuncSetAttribute(knn_gemm_kernel,
                         cudaFuncAttributeMaxDynamicSharedMemorySize, SMEM_TOTAL);

    conv_kernel<<<(N_TRAIN + N_TEST) / 8, 256>>>(Xtr, Xte);
    knn_gemm_kernel<<<NCTAS, 512, SMEM_TOTAL>>>();
    rescue_kernel<<<N_TEST / 8, 256>>>(Xtr, Xte, yw, out);
}